// round 7
// baseline (speedup 1.0000x reference)
#include <cuda_runtime.h>
#include <cuda_bf16.h>
#include <cstdint>

// ---------------------------------------------------------------------------
// GraphAutoencoder (sm_100 base): scatter-mean -> encoder GEMM -> decoder GEMM
// R7: factored split-GEMM. Per K-chunk load Ah,Al,Bh,Bl once; 3 MMA pairings
// (Ah*Bh + Ah*Bl + Al*Bh) into one fp32 accumulator. K=512, BK=32, 2-stage.
// ---------------------------------------------------------------------------

#define N_NODES_MAX 50000
#define IN_DIM      256
#define HID_DIM     512
#define OUT_DIM     256
#define KDIM        512
#define NCHUNK      16          // KDIM / 32

// ------------------------------ scratch ------------------------------------
__device__ __align__(16) float g_neigh[N_NODES_MAX * IN_DIM];
__device__ float g_deg[N_NODES_MAX];
__device__ __align__(16) __nv_bfloat16 g_eAh[N_NODES_MAX * 512];   // [x | nmean] hi
__device__ __align__(16) __nv_bfloat16 g_eAl[N_NODES_MAX * 512];   // [x | nmean] lo
__device__ __align__(16) __nv_bfloat16 g_hh[N_NODES_MAX * HID_DIM];
__device__ __align__(16) __nv_bfloat16 g_hl[N_NODES_MAX * HID_DIM];
__device__ __align__(16) __nv_bfloat16 g_BeH[KDIM * HID_DIM];
__device__ __align__(16) __nv_bfloat16 g_BeL[KDIM * HID_DIM];
__device__ __align__(16) __nv_bfloat16 g_BdH[KDIM * OUT_DIM];
__device__ __align__(16) __nv_bfloat16 g_BdL[KDIM * OUT_DIM];
__device__ __align__(16) float g_hfb[N_NODES_MAX * HID_DIM];

// --------------------------- asm helpers -----------------------------------
__device__ __forceinline__ uint32_t smem_u32(const void* p) {
    uint32_t a;
    asm("{ .reg .u64 t; cvta.to.shared.u64 t, %1; cvt.u32.u64 %0, t; }"
        : "=r"(a) : "l"(p));
    return a;
}
__device__ __forceinline__ void cp16(uint32_t dst, const void* src, uint32_t srcsize) {
    asm volatile("cp.async.cg.shared.global [%0], [%1], 16, %2;"
                 :: "r"(dst), "l"(src), "r"(srcsize) : "memory");
}
__device__ __forceinline__ void cp_commit() {
    asm volatile("cp.async.commit_group;" ::: "memory");
}
template <int N>
__device__ __forceinline__ void cp_wait() {
    asm volatile("cp.async.wait_group %0;" :: "n"(N) : "memory");
}
#define LDSM_X4(r0, r1, r2, r3, a) \
    asm volatile("ldmatrix.sync.aligned.m8n8.x4.shared.b16 {%0,%1,%2,%3}, [%4];" \
                 : "=r"(r0), "=r"(r1), "=r"(r2), "=r"(r3) : "r"(a))
#define LDSM_X4_T(r0, r1, r2, r3, a) \
    asm volatile("ldmatrix.sync.aligned.m8n8.x4.trans.shared.b16 {%0,%1,%2,%3}, [%4];" \
                 : "=r"(r0), "=r"(r1), "=r"(r2), "=r"(r3) : "r"(a))
#define MMA16816(c, a0, a1, a2, a3, b0, b1) \
    asm volatile("mma.sync.aligned.m16n8k16.row.col.f32.bf16.bf16.f32 " \
                 "{%0,%1,%2,%3}, {%4,%5,%6,%7}, {%8,%9}, {%0,%1,%2,%3};" \
                 : "+f"((c)[0]), "+f"((c)[1]), "+f"((c)[2]), "+f"((c)[3]) \
                 : "r"(a0), "r"(a1), "r"(a2), "r"(a3), "r"(b0), "r"(b1))

// ----------------------------- prep kernels --------------------------------
__global__ void prep0_kernel(const float* __restrict__ x, int M) {
    int i = blockIdx.x * blockDim.x + threadIdx.x;
    if (i >= M * IN_DIM) return;
    g_neigh[i] = 0.f;
    int r = i >> 8, c = i & 255;
    float v = x[i];
    __nv_bfloat16 hi = __float2bfloat16(v);
    g_eAh[(size_t)r * 512 + c] = hi;
    g_eAl[(size_t)r * 512 + c] = __float2bfloat16(v - __bfloat162float(hi));
    if (i < M) g_deg[i] = 0.f;
}

__global__ void scatter_kernel(const float* __restrict__ x,
                               const int* __restrict__ src,
                               const int* __restrict__ dst,
                               int n_edges) {
    const int CH = IN_DIM / 4;
    long long total = (long long)n_edges * CH;
    long long i = (long long)blockIdx.x * blockDim.x + threadIdx.x;
    if (i >= total) return;
    int e = (int)(i >> 6), c = (int)(i & 63);
    int s = src[e], d = dst[e];
    if (c == 0) atomicAdd(&g_deg[d], 1.0f);
    float4 v = reinterpret_cast<const float4*>(x)[(long long)s * CH + c];
    atomicAdd(reinterpret_cast<float4*>(g_neigh) + (long long)d * CH + c, v);
}

__global__ void prep1_kernel(const float* __restrict__ Wself,
                             const float* __restrict__ Wneigh,
                             const float* __restrict__ Wdec, int M) {
    int i = blockIdx.x * blockDim.x + threadIdx.x;
    int nx = M * IN_DIM;
    if (i < nx) {
        int r = i >> 8, c = i & 255;
        float v = g_neigh[i] / fmaxf(g_deg[r], 1.0f);
        __nv_bfloat16 hi = __float2bfloat16(v);
        g_eAh[(size_t)r * 512 + 256 + c] = hi;
        g_eAl[(size_t)r * 512 + 256 + c] = __float2bfloat16(v - __bfloat162float(hi));
        return;
    }
    int j = i - nx;
    if (j < KDIM * HID_DIM) {
        int k = j >> 9, n = j & 511;
        float w = (k < 256) ? Wself[k * HID_DIM + n] : Wneigh[(k - 256) * HID_DIM + n];
        __nv_bfloat16 hi = __float2bfloat16(w);
        g_BeH[j] = hi;
        g_BeL[j] = __float2bfloat16(w - __bfloat162float(hi));
        return;
    }
    j -= KDIM * HID_DIM;
    if (j < KDIM * OUT_DIM) {
        int k = j >> 8, n = j & 255;
        float w = Wdec[k * OUT_DIM + n];
        __nv_bfloat16 hi = __float2bfloat16(w);
        g_BdH[j] = hi;
        g_BdL[j] = __float2bfloat16(w - __bfloat162float(hi));
    }
}

// ----------------------------- mma GEMM ------------------------------------
// CTA 128x128, 4 warps (2M x 2N), warp 64x64, BK=32, 2-stage, factored split.
#define A_PITCH 80            // bytes: 32 bf16 + 8 pad
#define B_PITCH 272           // bytes: 128 bf16 + 8 pad
#define TILE_A (128 * A_PITCH)       // 10240 B (one of Ah/Al)
#define TILE_B (32 * B_PITCH)        // 8704 B  (one of Bh/Bl)
#define STAGE_SZ (2 * TILE_A + 2 * TILE_B)   // 37888 B
#define STAGES 2
#define SMEM_DYN (STAGES * STAGE_SZ)         // 75776 B

template <bool RELU, bool SPLIT>
__global__ __launch_bounds__(128, 2)
void gemm_mma(const __nv_bfloat16* __restrict__ Ah,
              const __nv_bfloat16* __restrict__ Al,
              const __nv_bfloat16* __restrict__ BH,
              const __nv_bfloat16* __restrict__ BL,
              const float* __restrict__ bias,
              float* __restrict__ C,
              __nv_bfloat16* __restrict__ oH, __nv_bfloat16* __restrict__ oL,
              int M, int N) {
    extern __shared__ __align__(16) unsigned char smem[];
    uint32_t sbase = smem_u32(smem);

    int tid = threadIdx.x;
    int wid = tid >> 5, lane = tid & 31;
    int wm = wid & 1, wn = wid >> 1;
    int rowBase = blockIdx.y * 128;
    int colBase = blockIdx.x * 128;

    float c[4][8][4];
#pragma unroll
    for (int mf = 0; mf < 4; mf++)
#pragma unroll
        for (int nf = 0; nf < 8; nf++)
#pragma unroll
            for (int q = 0; q < 4; q++) c[mf][nf][q] = 0.f;

    // stage layout: [Ah | Al | Bh | Bl]
    auto load_chunk = [&](int buf, int ch) {
        uint32_t st = sbase + buf * STAGE_SZ;
        int k0 = ch * 32;
        // A tiles: 512 cp16 per matrix, 4 per thread
#pragma unroll
        for (int i = 0; i < 4; i++) {
            int idx = tid + i * 128;
            int r = idx >> 2, cs = idx & 3;
            int grow = rowBase + r;
            int srow = grow < M ? grow : M - 1;
            uint32_t sz = grow < M ? 16u : 0u;
            size_t go = (size_t)srow * 512 + k0 + cs * 8;
            cp16(st + r * A_PITCH + cs * 16, Ah + go, sz);
            cp16(st + TILE_A + r * A_PITCH + cs * 16, Al + go, sz);
        }
        // B tiles: 512 cp16 per matrix, 4 per thread
#pragma unroll
        for (int i = 0; i < 4; i++) {
            int idx = tid + i * 128;
            int r = idx >> 4, cs = idx & 15;
            size_t go = (size_t)(k0 + r) * N + colBase + cs * 8;
            cp16(st + 2 * TILE_A + r * B_PITCH + cs * 16, BH + go, 16u);
            cp16(st + 2 * TILE_A + TILE_B + r * B_PITCH + cs * 16, BL + go, 16u);
        }
        cp_commit();
    };

    uint32_t aOff = (uint32_t)((wm * 64 + (lane & 15)) * A_PITCH + (lane >> 4) * 16);
    uint32_t bOff = (uint32_t)((lane & 15) * B_PITCH + wn * 128 + (lane >> 4) * 16);

    load_chunk(0, 0);

    for (int ch = 0; ch < NCHUNK; ch++) {
        int buf = ch & 1;
        cp_wait<0>();
        __syncthreads();
        if (ch + 1 < NCHUNK) load_chunk(buf ^ 1, ch + 1);

        uint32_t st = sbase + buf * STAGE_SZ;
        uint32_t aHB = st + aOff;
        uint32_t aLB = st + TILE_A + aOff;
        uint32_t bHB = st + 2 * TILE_A + bOff;
        uint32_t bLB = st + 2 * TILE_A + TILE_B + bOff;

#pragma unroll
        for (int kk = 0; kk < 2; kk++) {
            uint32_t ah[16], al[16], bh[16], bl[16];
#pragma unroll
            for (int g = 0; g < 4; g++) {
                LDSM_X4(ah[4 * g], ah[4 * g + 1], ah[4 * g + 2], ah[4 * g + 3],
                        aHB + g * 16 * A_PITCH + kk * 32);
                LDSM_X4(al[4 * g], al[4 * g + 1], al[4 * g + 2], al[4 * g + 3],
                        aLB + g * 16 * A_PITCH + kk * 32);
            }
#pragma unroll
            for (int p = 0; p < 4; p++) {
                LDSM_X4_T(bh[4 * p], bh[4 * p + 1], bh[4 * p + 2], bh[4 * p + 3],
                          bHB + kk * 16 * B_PITCH + p * 32);
                LDSM_X4_T(bl[4 * p], bl[4 * p + 1], bl[4 * p + 2], bl[4 * p + 3],
                          bLB + kk * 16 * B_PITCH + p * 32);
            }
            // pairing 1: Ah * Bh
#pragma unroll
            for (int mf = 0; mf < 4; mf++)
#pragma unroll
                for (int nf = 0; nf < 8; nf++) {
                    uint32_t* bp = bh + (nf >> 1) * 4 + (nf & 1) * 2;
                    MMA16816(c[mf][nf], ah[4 * mf], ah[4 * mf + 1],
                             ah[4 * mf + 2], ah[4 * mf + 3], bp[0], bp[1]);
                }
            // pairing 2: Ah * Bl
#pragma unroll
            for (int mf = 0; mf < 4; mf++)
#pragma unroll
                for (int nf = 0; nf < 8; nf++) {
                    uint32_t* bp = bl + (nf >> 1) * 4 + (nf & 1) * 2;
                    MMA16816(c[mf][nf], ah[4 * mf], ah[4 * mf + 1],
                             ah[4 * mf + 2], ah[4 * mf + 3], bp[0], bp[1]);
                }
            // pairing 3: Al * Bh
#pragma unroll
            for (int mf = 0; mf < 4; mf++)
#pragma unroll
                for (int nf = 0; nf < 8; nf++) {
                    uint32_t* bp = bh + (nf >> 1) * 4 + (nf & 1) * 2;
                    MMA16816(c[mf][nf], al[4 * mf], al[4 * mf + 1],
                             al[4 * mf + 2], al[4 * mf + 3], bp[0], bp[1]);
                }
        }
    }

    // ---- epilogue ----
    int groupID = lane >> 2, tid4 = lane & 3;
#pragma unroll
    for (int mf = 0; mf < 4; mf++) {
        int r0 = rowBase + wm * 64 + mf * 16 + groupID;
#pragma unroll
        for (int nf = 0; nf < 8; nf++) {
            int cb = colBase + wn * 64 + nf * 8 + tid4 * 2;
            float b0 = bias[cb], b1 = bias[cb + 1];
#pragma unroll
            for (int hh = 0; hh < 2; hh++) {
                int r = r0 + hh * 8;
                if (r >= M) continue;
                float v0 = c[mf][nf][2 * hh + 0] + b0;
                float v1 = c[mf][nf][2 * hh + 1] + b1;
                if (RELU) { v0 = fmaxf(v0, 0.f); v1 = fmaxf(v1, 0.f); }
                *reinterpret_cast<float2*>(C + (size_t)r * N + cb) =
                    make_float2(v0, v1);
                if (SPLIT) {
                    __nv_bfloat16 h0 = __float2bfloat16(v0);
                    __nv_bfloat16 h1 = __float2bfloat16(v1);
                    __nv_bfloat162 hv; hv.x = h0; hv.y = h1;
                    *reinterpret_cast<__nv_bfloat162*>(oH + (size_t)r * N + cb) = hv;
                    __nv_bfloat162 lv;
                    lv.x = __float2bfloat16(v0 - __bfloat162float(h0));
                    lv.y = __float2bfloat16(v1 - __bfloat162float(h1));
                    *reinterpret_cast<__nv_bfloat162*>(oL + (size_t)r * N + cb) = lv;
                }
            }
        }
    }
}

// ------------------------------ launch -------------------------------------
extern "C" void kernel_launch(void* const* d_in, const int* in_sizes, int n_in,
                              void* d_out, int out_size) {
    const float* x       = (const float*)d_in[0];
    const int*   src     = (const int*)d_in[1];
    const int*   dst     = (const int*)d_in[2];
    const float* W_self  = (const float*)d_in[3];
    const float* W_neigh = (const float*)d_in[4];
    const float* b_enc   = (const float*)d_in[5];
    const float* W_dec   = (const float*)d_in[6];
    const float* b_dec   = (const float*)d_in[7];

    int M  = in_sizes[0] / IN_DIM;
    int nE = in_sizes[1];

    float* out = (float*)d_out;
    float* h;
    if (out_size == M * (OUT_DIM + HID_DIM)) {
        h = out + (long long)M * OUT_DIM;
    } else {
        void* p = nullptr;
        cudaGetSymbolAddress(&p, g_hfb);
        h = (float*)p;
    }

    void *p_eAh, *p_eAl, *p_hh, *p_hl, *p_beH, *p_beL, *p_bdH, *p_bdL;
    cudaGetSymbolAddress(&p_eAh, g_eAh); cudaGetSymbolAddress(&p_eAl, g_eAl);
    cudaGetSymbolAddress(&p_hh, g_hh);   cudaGetSymbolAddress(&p_hl, g_hl);
    cudaGetSymbolAddress(&p_beH, g_BeH); cudaGetSymbolAddress(&p_beL, g_BeL);
    cudaGetSymbolAddress(&p_bdH, g_BdH); cudaGetSymbolAddress(&p_bdL, g_BdL);

    cudaFuncSetAttribute(gemm_mma<true, true>,
                         cudaFuncAttributeMaxDynamicSharedMemorySize, SMEM_DYN);
    cudaFuncSetAttribute(gemm_mma<false, false>,
                         cudaFuncAttributeMaxDynamicSharedMemorySize, SMEM_DYN);

    // 1) zero neigh/deg + split x into combined A
    prep0_kernel<<<(M * IN_DIM + 255) / 256, 256>>>(x, M);
    // 2) scatter (degree fused)
    {
        long long items = (long long)nE * (IN_DIM / 4);
        scatter_kernel<<<(int)((items + 255) / 256), 256>>>(x, src, dst, nE);
    }
    // 3) neigh-mean split + weight packing (hi/lo)
    {
        int total = M * IN_DIM + KDIM * HID_DIM + KDIM * OUT_DIM;
        prep1_kernel<<<(total + 255) / 256, 256>>>(W_self, W_neigh, W_dec, M);
    }
    // 4) encoder GEMM: h = relu(A @ Benc + b_enc), emit h hi/lo
    {
        dim3 grid(HID_DIM / 128, (M + 127) / 128);
        gemm_mma<true, true><<<grid, 128, SMEM_DYN>>>(
            (const __nv_bfloat16*)p_eAh, (const __nv_bfloat16*)p_eAl,
            (const __nv_bfloat16*)p_beH, (const __nv_bfloat16*)p_beL,
            b_enc, h, (__nv_bfloat16*)p_hh, (__nv_bfloat16*)p_hl, M, HID_DIM);
    }
    // 5) decoder GEMM: out = h @ Bdec + b_dec
    {
        dim3 grid(OUT_DIM / 128, (M + 127) / 128);
        gemm_mma<false, false><<<grid, 128, SMEM_DYN>>>(
            (const __nv_bfloat16*)p_hh, (const __nv_bfloat16*)p_hl,
            (const __nv_bfloat16*)p_bdH, (const __nv_bfloat16*)p_bdL,
            b_dec, out, nullptr, nullptr, M, OUT_DIM);
    }
}

// round 8
// speedup vs baseline: 1.5945x; 1.5945x over previous
#include <cuda_runtime.h>
#include <cuda_fp16.h>
#include <cstdint>

// ---------------------------------------------------------------------------
// GraphAutoencoder (sm_100 base): scatter-mean -> encoder GEMM -> decoder GEMM
// R8: single-pass fp16 mma.sync GEMMs (no error-split; norm rel_err ~3e-4).
// CTA 128x128, 4 warps (2x2, 64x64 tiles), BK=32, 3-stage cp.async pipe.
// ---------------------------------------------------------------------------

#define N_NODES_MAX 50000
#define IN_DIM      256
#define HID_DIM     512
#define OUT_DIM     256
#define KDIM        512
#define NCH         16           // KDIM / 32

// ------------------------------ scratch ------------------------------------
__device__ __align__(16) float g_neigh[N_NODES_MAX * IN_DIM];
__device__ float g_deg[N_NODES_MAX];
__device__ __align__(16) __half g_eA[N_NODES_MAX * KDIM];     // [x | nmean] fp16
__device__ __align__(16) __half g_hf[N_NODES_MAX * HID_DIM];  // h fp16
__device__ __align__(16) __half g_Benc[KDIM * HID_DIM];
__device__ __align__(16) __half g_Bdec[KDIM * OUT_DIM];
__device__ __align__(16) float g_hfb[N_NODES_MAX * HID_DIM];

// --------------------------- asm helpers -----------------------------------
__device__ __forceinline__ uint32_t smem_u32(const void* p) {
    uint32_t a;
    asm("{ .reg .u64 t; cvta.to.shared.u64 t, %1; cvt.u32.u64 %0, t; }"
        : "=r"(a) : "l"(p));
    return a;
}
__device__ __forceinline__ void cp16(uint32_t dst, const void* src, uint32_t srcsize) {
    asm volatile("cp.async.cg.shared.global [%0], [%1], 16, %2;"
                 :: "r"(dst), "l"(src), "r"(srcsize) : "memory");
}
__device__ __forceinline__ void cp_commit() {
    asm volatile("cp.async.commit_group;" ::: "memory");
}
template <int N>
__device__ __forceinline__ void cp_wait() {
    asm volatile("cp.async.wait_group %0;" :: "n"(N) : "memory");
}
#define LDSM_X4(r0, r1, r2, r3, a) \
    asm volatile("ldmatrix.sync.aligned.m8n8.x4.shared.b16 {%0,%1,%2,%3}, [%4];" \
                 : "=r"(r0), "=r"(r1), "=r"(r2), "=r"(r3) : "r"(a))
#define LDSM_X4_T(r0, r1, r2, r3, a) \
    asm volatile("ldmatrix.sync.aligned.m8n8.x4.trans.shared.b16 {%0,%1,%2,%3}, [%4];" \
                 : "=r"(r0), "=r"(r1), "=r"(r2), "=r"(r3) : "r"(a))
#define MMA16816(c, a0, a1, a2, a3, b0, b1) \
    asm volatile("mma.sync.aligned.m16n8k16.row.col.f32.f16.f16.f32 " \
                 "{%0,%1,%2,%3}, {%4,%5,%6,%7}, {%8,%9}, {%0,%1,%2,%3};" \
                 : "+f"((c)[0]), "+f"((c)[1]), "+f"((c)[2]), "+f"((c)[3]) \
                 : "r"(a0), "r"(a1), "r"(a2), "r"(a3), "r"(b0), "r"(b1))

// ----------------------------- prep kernels --------------------------------
__global__ void prep0_kernel(const float* __restrict__ x, int M) {
    int i = blockIdx.x * blockDim.x + threadIdx.x;
    if (i >= M * IN_DIM) return;
    g_neigh[i] = 0.f;
    int r = i >> 8, c = i & 255;
    g_eA[(size_t)r * KDIM + c] = __float2half(x[i]);
    if (i < M) g_deg[i] = 0.f;
}

__global__ void scatter_kernel(const float* __restrict__ x,
                               const int* __restrict__ src,
                               const int* __restrict__ dst,
                               int n_edges) {
    const int CH = IN_DIM / 4;
    long long total = (long long)n_edges * CH;
    long long i = (long long)blockIdx.x * blockDim.x + threadIdx.x;
    if (i >= total) return;
    int e = (int)(i >> 6), c = (int)(i & 63);
    int s = src[e], d = dst[e];
    if (c == 0) atomicAdd(&g_deg[d], 1.0f);
    float4 v = reinterpret_cast<const float4*>(x)[(long long)s * CH + c];
    atomicAdd(reinterpret_cast<float4*>(g_neigh) + (long long)d * CH + c, v);
}

__global__ void prep1_kernel(const float* __restrict__ Wself,
                             const float* __restrict__ Wneigh,
                             const float* __restrict__ Wdec, int M) {
    int i = blockIdx.x * blockDim.x + threadIdx.x;
    int nx = M * IN_DIM;
    if (i < nx) {
        int r = i >> 8, c = i & 255;
        float v = g_neigh[i] / fmaxf(g_deg[r], 1.0f);
        g_eA[(size_t)r * KDIM + 256 + c] = __float2half(v);
        return;
    }
    int j = i - nx;
    if (j < KDIM * HID_DIM) {
        int k = j >> 9, n = j & 511;
        float w = (k < 256) ? Wself[k * HID_DIM + n] : Wneigh[(k - 256) * HID_DIM + n];
        g_Benc[j] = __float2half(w);
        return;
    }
    j -= KDIM * HID_DIM;
    if (j < KDIM * OUT_DIM) {
        int k = j >> 8, n = j & 255;
        g_Bdec[j] = __float2half(Wdec[k * OUT_DIM + n]);
    }
}

// ----------------------------- mma GEMM ------------------------------------
// CTA 128x128, 4 warps (2M x 2N), warp tile 64x64, BK=32, 3-stage pipe.
#define A_PITCH 80
#define B_PITCH 272
#define SZA (128 * A_PITCH)   // 10240 B
#define SZB (32 * B_PITCH)    // 8704 B
#define STAGES 3
#define SMEM_DYN (STAGES * (SZA + SZB))   // 56832 B

template <bool RELU, bool EMITH>
__global__ __launch_bounds__(128, 2)
void gemm_mma(const __half* __restrict__ A,
              const __half* __restrict__ Bp,
              const float* __restrict__ bias,
              float* __restrict__ C,
              __half* __restrict__ oH,
              int M, int N) {
    extern __shared__ __align__(16) unsigned char smem[];
    uint32_t sA = smem_u32(smem);
    uint32_t sB = sA + STAGES * SZA;

    int tid = threadIdx.x;
    int wid = tid >> 5, lane = tid & 31;
    int wm = wid & 1, wn = wid >> 1;
    int rowBase = blockIdx.y * 128;
    int colBase = blockIdx.x * 128;

    float c[4][8][4];
#pragma unroll
    for (int mf = 0; mf < 4; mf++)
#pragma unroll
        for (int nf = 0; nf < 8; nf++)
#pragma unroll
            for (int q = 0; q < 4; q++) c[mf][nf][q] = 0.f;

    auto load_chunk = [&](int buf, int ch) {
        int k0 = ch * 32;
#pragma unroll
        for (int i = 0; i < 4; i++) {
            int idx = tid + i * 128;
            int r = idx >> 2, cs = idx & 3;
            int grow = rowBase + r;
            int srow = grow < M ? grow : M - 1;
            cp16(sA + buf * SZA + r * A_PITCH + cs * 16,
                 A + (size_t)srow * KDIM + k0 + cs * 8,
                 grow < M ? 16u : 0u);
        }
#pragma unroll
        for (int i = 0; i < 4; i++) {
            int idx = tid + i * 128;
            int r = idx >> 4, cs = idx & 15;
            cp16(sB + buf * SZB + r * B_PITCH + cs * 16,
                 Bp + (size_t)(k0 + r) * N + colBase + cs * 8, 16u);
        }
        cp_commit();
    };

    uint32_t aAddr = sA + (wm * 64 + (lane & 15)) * A_PITCH + (lane >> 4) * 16;
    uint32_t bAddr = sB + (lane & 15) * B_PITCH + wn * 128 + (lane >> 4) * 16;

    load_chunk(0, 0);
    load_chunk(1, 1);

    for (int ch = 0; ch < NCH; ch++) {
        int buf = ch % STAGES;
        if (ch == NCH - 1) cp_wait<0>();
        else               cp_wait<1>();
        __syncthreads();
        if (ch + 2 < NCH) load_chunk((ch + 2) % STAGES, ch + 2);

        uint32_t aB = aAddr + buf * SZA;
        uint32_t bB = bAddr + buf * SZB;
#pragma unroll
        for (int kk = 0; kk < 2; kk++) {
            uint32_t a[16];
#pragma unroll
            for (int g = 0; g < 4; g++)
                LDSM_X4(a[4 * g], a[4 * g + 1], a[4 * g + 2], a[4 * g + 3],
                        aB + g * 16 * A_PITCH + kk * 32);
            uint32_t b[16];
#pragma unroll
            for (int p = 0; p < 4; p++)
                LDSM_X4_T(b[4 * p], b[4 * p + 1], b[4 * p + 2], b[4 * p + 3],
                          bB + kk * 16 * B_PITCH + p * 32);
#pragma unroll
            for (int mf = 0; mf < 4; mf++)
#pragma unroll
                for (int nf = 0; nf < 8; nf++) {
                    uint32_t* bp = b + (nf >> 1) * 4 + (nf & 1) * 2;
                    MMA16816(c[mf][nf], a[4 * mf], a[4 * mf + 1],
                             a[4 * mf + 2], a[4 * mf + 3], bp[0], bp[1]);
                }
        }
    }

    // ---- epilogue ----
    int groupID = lane >> 2, tid4 = lane & 3;
#pragma unroll
    for (int mf = 0; mf < 4; mf++) {
        int r0 = rowBase + wm * 64 + mf * 16 + groupID;
#pragma unroll
        for (int nf = 0; nf < 8; nf++) {
            int cb = colBase + wn * 64 + nf * 8 + tid4 * 2;
            float b0 = bias[cb], b1 = bias[cb + 1];
#pragma unroll
            for (int hh = 0; hh < 2; hh++) {
                int r = r0 + hh * 8;
                if (r >= M) continue;
                float v0 = c[mf][nf][2 * hh + 0] + b0;
                float v1 = c[mf][nf][2 * hh + 1] + b1;
                if (RELU) { v0 = fmaxf(v0, 0.f); v1 = fmaxf(v1, 0.f); }
                *reinterpret_cast<float2*>(C + (size_t)r * N + cb) =
                    make_float2(v0, v1);
                if (EMITH) {
                    __half2 hv;
                    hv.x = __float2half(v0);
                    hv.y = __float2half(v1);
                    *reinterpret_cast<__half2*>(oH + (size_t)r * N + cb) = hv;
                }
            }
        }
    }
}

// ------------------------------ launch -------------------------------------
extern "C" void kernel_launch(void* const* d_in, const int* in_sizes, int n_in,
                              void* d_out, int out_size) {
    const float* x       = (const float*)d_in[0];
    const int*   src     = (const int*)d_in[1];
    const int*   dst     = (const int*)d_in[2];
    const float* W_self  = (const float*)d_in[3];
    const float* W_neigh = (const float*)d_in[4];
    const float* b_enc   = (const float*)d_in[5];
    const float* W_dec   = (const float*)d_in[6];
    const float* b_dec   = (const float*)d_in[7];

    int M  = in_sizes[0] / IN_DIM;
    int nE = in_sizes[1];

    float* out = (float*)d_out;
    float* h;
    if (out_size == M * (OUT_DIM + HID_DIM)) {
        h = out + (long long)M * OUT_DIM;
    } else {
        void* p = nullptr;
        cudaGetSymbolAddress(&p, g_hfb);
        h = (float*)p;
    }

    void *p_eA, *p_hf, *p_be, *p_bd;
    cudaGetSymbolAddress(&p_eA, g_eA);
    cudaGetSymbolAddress(&p_hf, g_hf);
    cudaGetSymbolAddress(&p_be, g_Benc);
    cudaGetSymbolAddress(&p_bd, g_Bdec);

    cudaFuncSetAttribute(gemm_mma<true, true>,
                         cudaFuncAttributeMaxDynamicSharedMemorySize, SMEM_DYN);
    cudaFuncSetAttribute(gemm_mma<false, false>,
                         cudaFuncAttributeMaxDynamicSharedMemorySize, SMEM_DYN);

    // 1) zero neigh/deg + convert x to fp16
    prep0_kernel<<<(M * IN_DIM + 255) / 256, 256>>>(x, M);
    // 2) scatter (degree fused)
    {
        long long items = (long long)nE * (IN_DIM / 4);
        scatter_kernel<<<(int)((items + 255) / 256), 256>>>(x, src, dst, nE);
    }
    // 3) neigh-mean fp16 + weight packing fp16
    {
        int total = M * IN_DIM + KDIM * HID_DIM + KDIM * OUT_DIM;
        prep1_kernel<<<(total + 255) / 256, 256>>>(W_self, W_neigh, W_dec, M);
    }
    // 4) encoder GEMM: h = relu(A @ Benc + b_enc), emit h fp16
    {
        dim3 grid(HID_DIM / 128, (M + 127) / 128);
        gemm_mma<true, true><<<grid, 128, SMEM_DYN>>>(
            (const __half*)p_eA, (const __half*)p_be, b_enc, h,
            (__half*)p_hf, M, HID_DIM);
    }
    // 5) decoder GEMM: out = h @ Bdec + b_dec
    {
        dim3 grid(OUT_DIM / 128, (M + 127) / 128);
        gemm_mma<false, false><<<grid, 128, SMEM_DYN>>>(
            (const __half*)p_hf, (const __half*)p_bd, b_dec, out,
            nullptr, M, OUT_DIM);
    }
}

// round 9
// speedup vs baseline: 2.0625x; 1.2935x over previous
#include <cuda_runtime.h>
#include <cuda_fp16.h>
#include <cstdint>

// ---------------------------------------------------------------------------
// GraphAutoencoder (sm_100 base), R9:
//  counting-sort scatter (no float atomics) -> fp16 gather aggregation ->
//  fp16 mma.sync encoder/decoder GEMMs (CTA 128x128, 4 warps, 3-stage pipe).
// ---------------------------------------------------------------------------

#define N_NODES_MAX 50000
#define N_EDGES_MAX 1000000
#define IN_DIM      256
#define HID_DIM     512
#define OUT_DIM     256
#define KDIM        512
#define NCH         16           // KDIM / 32

// ------------------------------ scratch ------------------------------------
__device__ int g_cnt[N_NODES_MAX];
__device__ int g_offs[N_NODES_MAX + 1];
__device__ int g_cur[N_NODES_MAX];
__device__ int g_srt[N_EDGES_MAX];
__device__ __align__(16) __half g_eA[N_NODES_MAX * KDIM];     // [x | nmean] fp16
__device__ __align__(16) __half g_hf[N_NODES_MAX * HID_DIM];  // h fp16
__device__ __align__(16) __half g_Benc[KDIM * HID_DIM];
__device__ __align__(16) __half g_Bdec[KDIM * OUT_DIM];
__device__ __align__(16) float g_hfb[N_NODES_MAX * HID_DIM];

// --------------------------- asm helpers -----------------------------------
__device__ __forceinline__ uint32_t smem_u32(const void* p) {
    uint32_t a;
    asm("{ .reg .u64 t; cvta.to.shared.u64 t, %1; cvt.u32.u64 %0, t; }"
        : "=r"(a) : "l"(p));
    return a;
}
__device__ __forceinline__ void cp16(uint32_t dst, const void* src, uint32_t srcsize) {
    asm volatile("cp.async.cg.shared.global [%0], [%1], 16, %2;"
                 :: "r"(dst), "l"(src), "r"(srcsize) : "memory");
}
__device__ __forceinline__ void cp_commit() {
    asm volatile("cp.async.commit_group;" ::: "memory");
}
template <int N>
__device__ __forceinline__ void cp_wait() {
    asm volatile("cp.async.wait_group %0;" :: "n"(N) : "memory");
}
#define LDSM_X4(r0, r1, r2, r3, a) \
    asm volatile("ldmatrix.sync.aligned.m8n8.x4.shared.b16 {%0,%1,%2,%3}, [%4];" \
                 : "=r"(r0), "=r"(r1), "=r"(r2), "=r"(r3) : "r"(a))
#define LDSM_X4_T(r0, r1, r2, r3, a) \
    asm volatile("ldmatrix.sync.aligned.m8n8.x4.trans.shared.b16 {%0,%1,%2,%3}, [%4];" \
                 : "=r"(r0), "=r"(r1), "=r"(r2), "=r"(r3) : "r"(a))
#define MMA16816(c, a0, a1, a2, a3, b0, b1) \
    asm volatile("mma.sync.aligned.m16n8k16.row.col.f32.f16.f16.f32 " \
                 "{%0,%1,%2,%3}, {%4,%5,%6,%7}, {%8,%9}, {%0,%1,%2,%3};" \
                 : "+f"((c)[0]), "+f"((c)[1]), "+f"((c)[2]), "+f"((c)[3]) \
                 : "r"(a0), "r"(a1), "r"(a2), "r"(a3), "r"(b0), "r"(b1))

// ----------------------------- prep kernels --------------------------------
// x -> fp16 into g_eA[:, 0:256]; pack Benc/Bdec fp16
__global__ void prep0_kernel(const float* __restrict__ x,
                             const float* __restrict__ Wself,
                             const float* __restrict__ Wneigh,
                             const float* __restrict__ Wdec, int M) {
    int i = blockIdx.x * blockDim.x + threadIdx.x;
    int nx = M * IN_DIM;
    if (i < nx) {
        int r = i >> 8, c = i & 255;
        g_eA[(size_t)r * KDIM + c] = __float2half(x[i]);
        return;
    }
    int j = i - nx;
    if (j < KDIM * HID_DIM) {
        int k = j >> 9, n = j & 511;
        float w = (k < 256) ? Wself[k * HID_DIM + n] : Wneigh[(k - 256) * HID_DIM + n];
        g_Benc[j] = __float2half(w);
        return;
    }
    j -= KDIM * HID_DIM;
    if (j < KDIM * OUT_DIM) {
        int k = j >> 8, n = j & 255;
        g_Bdec[j] = __float2half(Wdec[k * OUT_DIM + n]);
    }
}

__global__ void hist_kernel(const int* __restrict__ dst, int n_edges) {
    int i = blockIdx.x * blockDim.x + threadIdx.x;
    if (i < n_edges) atomicAdd(&g_cnt[dst[i]], 1);
}

// single-block exclusive scan over M counts -> offs[0..M], cur = offs copy
__global__ __launch_bounds__(1024)
void scan_kernel(int M) {
    __shared__ int sums[1024];
    int t = threadIdx.x;
    int chunk = (M + 1023) / 1024;
    int base = t * chunk;
    int s = 0;
    for (int i = 0; i < chunk; i++) {
        int idx = base + i;
        if (idx < M) s += g_cnt[idx];
    }
    sums[t] = s;
    __syncthreads();
    // Hillis-Steele inclusive scan
    for (int d = 1; d < 1024; d <<= 1) {
        int v = (t >= d) ? sums[t - d] : 0;
        __syncthreads();
        sums[t] += v;
        __syncthreads();
    }
    int prefix = (t == 0) ? 0 : sums[t - 1];
    for (int i = 0; i < chunk; i++) {
        int idx = base + i;
        if (idx < M) {
            g_offs[idx] = prefix;
            g_cur[idx] = prefix;
            prefix += g_cnt[idx];
        }
    }
    if (t == 1023) g_offs[M] = prefix;
}

__global__ void sortidx_kernel(const int* __restrict__ src,
                               const int* __restrict__ dst, int n_edges) {
    int i = blockIdx.x * blockDim.x + threadIdx.x;
    if (i >= n_edges) return;
    int pos = atomicAdd(&g_cur[dst[i]], 1);
    g_srt[pos] = src[i];
}

// one warp per node: gather fp16 rows, accumulate fp32, write fp16 mean
__global__ __launch_bounds__(256)
void aggregate_kernel(int M) {
    int wid_in_blk = threadIdx.x >> 5;
    int lane = threadIdx.x & 31;
    int node = blockIdx.x * 8 + wid_in_blk;
    if (node >= M) return;
    int beg = g_offs[node], end = g_offs[node + 1];

    float acc[8] = {0.f, 0.f, 0.f, 0.f, 0.f, 0.f, 0.f, 0.f};
    for (int e = beg; e < end; e++) {
        int s = g_srt[e];
        uint4 v = *reinterpret_cast<const uint4*>(
            g_eA + (size_t)s * KDIM + lane * 8);
        const __half2* h2 = reinterpret_cast<const __half2*>(&v);
#pragma unroll
        for (int q = 0; q < 4; q++) {
            float2 f = __half22float2(h2[q]);
            acc[2 * q + 0] += f.x;
            acc[2 * q + 1] += f.y;
        }
    }
    float inv = 1.0f / fmaxf((float)(end - beg), 1.0f);
    __half2 outv[4];
#pragma unroll
    for (int q = 0; q < 4; q++)
        outv[q] = __floats2half2_rn(acc[2 * q] * inv, acc[2 * q + 1] * inv);
    *reinterpret_cast<uint4*>(g_eA + (size_t)node * KDIM + 256 + lane * 8) =
        *reinterpret_cast<uint4*>(outv);
}

// ----------------------------- mma GEMM ------------------------------------
#define A_PITCH 80
#define B_PITCH 272
#define SZA (128 * A_PITCH)
#define SZB (32 * B_PITCH)
#define STAGES 3
#define SMEM_DYN (STAGES * (SZA + SZB))   // 56832 B

template <bool RELU, bool EMITH>
__global__ __launch_bounds__(128, 2)
void gemm_mma(const __half* __restrict__ A,
              const __half* __restrict__ Bp,
              const float* __restrict__ bias,
              float* __restrict__ C,
              __half* __restrict__ oH,
              int M, int N) {
    extern __shared__ __align__(16) unsigned char smem[];
    uint32_t sA = smem_u32(smem);
    uint32_t sB = sA + STAGES * SZA;

    int tid = threadIdx.x;
    int wid = tid >> 5, lane = tid & 31;
    int wm = wid & 1, wn = wid >> 1;
    int rowBase = blockIdx.y * 128;
    int colBase = blockIdx.x * 128;

    float c[4][8][4];
#pragma unroll
    for (int mf = 0; mf < 4; mf++)
#pragma unroll
        for (int nf = 0; nf < 8; nf++)
#pragma unroll
            for (int q = 0; q < 4; q++) c[mf][nf][q] = 0.f;

    auto load_chunk = [&](int buf, int ch) {
        int k0 = ch * 32;
#pragma unroll
        for (int i = 0; i < 4; i++) {
            int idx = tid + i * 128;
            int r = idx >> 2, cs = idx & 3;
            int grow = rowBase + r;
            int srow = grow < M ? grow : M - 1;
            cp16(sA + buf * SZA + r * A_PITCH + cs * 16,
                 A + (size_t)srow * KDIM + k0 + cs * 8,
                 grow < M ? 16u : 0u);
        }
#pragma unroll
        for (int i = 0; i < 4; i++) {
            int idx = tid + i * 128;
            int r = idx >> 4, cs = idx & 15;
            cp16(sB + buf * SZB + r * B_PITCH + cs * 16,
                 Bp + (size_t)(k0 + r) * N + colBase + cs * 8, 16u);
        }
        cp_commit();
    };

    uint32_t aAddr = sA + (wm * 64 + (lane & 15)) * A_PITCH + (lane >> 4) * 16;
    uint32_t bAddr = sB + (lane & 15) * B_PITCH + wn * 128 + (lane >> 4) * 16;

    load_chunk(0, 0);
    load_chunk(1, 1);

    for (int ch = 0; ch < NCH; ch++) {
        int buf = ch % STAGES;
        if (ch == NCH - 1) cp_wait<0>();
        else               cp_wait<1>();
        __syncthreads();
        if (ch + 2 < NCH) load_chunk((ch + 2) % STAGES, ch + 2);

        uint32_t aB = aAddr + buf * SZA;
        uint32_t bB = bAddr + buf * SZB;
#pragma unroll
        for (int kk = 0; kk < 2; kk++) {
            uint32_t a[16];
#pragma unroll
            for (int g = 0; g < 4; g++)
                LDSM_X4(a[4 * g], a[4 * g + 1], a[4 * g + 2], a[4 * g + 3],
                        aB + g * 16 * A_PITCH + kk * 32);
            uint32_t b[16];
#pragma unroll
            for (int p = 0; p < 4; p++)
                LDSM_X4_T(b[4 * p], b[4 * p + 1], b[4 * p + 2], b[4 * p + 3],
                          bB + kk * 16 * B_PITCH + p * 32);
#pragma unroll
            for (int mf = 0; mf < 4; mf++)
#pragma unroll
                for (int nf = 0; nf < 8; nf++) {
                    uint32_t* bp = b + (nf >> 1) * 4 + (nf & 1) * 2;
                    MMA16816(c[mf][nf], a[4 * mf], a[4 * mf + 1],
                             a[4 * mf + 2], a[4 * mf + 3], bp[0], bp[1]);
                }
        }
    }

    int groupID = lane >> 2, tid4 = lane & 3;
#pragma unroll
    for (int mf = 0; mf < 4; mf++) {
        int r0 = rowBase + wm * 64 + mf * 16 + groupID;
#pragma unroll
        for (int nf = 0; nf < 8; nf++) {
            int cb = colBase + wn * 64 + nf * 8 + tid4 * 2;
            float b0 = bias[cb], b1 = bias[cb + 1];
#pragma unroll
            for (int hh = 0; hh < 2; hh++) {
                int r = r0 + hh * 8;
                if (r >= M) continue;
                float v0 = c[mf][nf][2 * hh + 0] + b0;
                float v1 = c[mf][nf][2 * hh + 1] + b1;
                if (RELU) { v0 = fmaxf(v0, 0.f); v1 = fmaxf(v1, 0.f); }
                *reinterpret_cast<float2*>(C + (size_t)r * N + cb) =
                    make_float2(v0, v1);
                if (EMITH) {
                    __half2 hv;
                    hv.x = __float2half(v0);
                    hv.y = __float2half(v1);
                    *reinterpret_cast<__half2*>(oH + (size_t)r * N + cb) = hv;
                }
            }
        }
    }
}

// ------------------------------ launch -------------------------------------
extern "C" void kernel_launch(void* const* d_in, const int* in_sizes, int n_in,
                              void* d_out, int out_size) {
    const float* x       = (const float*)d_in[0];
    const int*   src     = (const int*)d_in[1];
    const int*   dst     = (const int*)d_in[2];
    const float* W_self  = (const float*)d_in[3];
    const float* W_neigh = (const float*)d_in[4];
    const float* b_enc   = (const float*)d_in[5];
    const float* W_dec   = (const float*)d_in[6];
    const float* b_dec   = (const float*)d_in[7];

    int M  = in_sizes[0] / IN_DIM;
    int nE = in_sizes[1];

    float* out = (float*)d_out;
    float* h;
    if (out_size == M * (OUT_DIM + HID_DIM)) {
        h = out + (long long)M * OUT_DIM;
    } else {
        void* p = nullptr;
        cudaGetSymbolAddress(&p, g_hfb);
        h = (float*)p;
    }

    void *p_eA, *p_hf, *p_be, *p_bd, *p_cnt;
    cudaGetSymbolAddress(&p_eA, g_eA);
    cudaGetSymbolAddress(&p_hf, g_hf);
    cudaGetSymbolAddress(&p_be, g_Benc);
    cudaGetSymbolAddress(&p_bd, g_Bdec);
    cudaGetSymbolAddress(&p_cnt, g_cnt);

    cudaFuncSetAttribute(gemm_mma<true, true>,
                         cudaFuncAttributeMaxDynamicSharedMemorySize, SMEM_DYN);
    cudaFuncSetAttribute(gemm_mma<false, false>,
                         cudaFuncAttributeMaxDynamicSharedMemorySize, SMEM_DYN);

    // 1) zero histogram + convert x / pack weights to fp16
    cudaMemsetAsync(p_cnt, 0, (size_t)M * sizeof(int), 0);
    {
        int total = M * IN_DIM + KDIM * HID_DIM + KDIM * OUT_DIM;
        prep0_kernel<<<(total + 255) / 256, 256>>>(x, W_self, W_neigh, W_dec, M);
    }
    // 2) degree histogram
    hist_kernel<<<(nE + 255) / 256, 256>>>(dst, nE);
    // 3) exclusive scan -> offsets + cursors
    scan_kernel<<<1, 1024>>>(M);
    // 4) sort edge sources by dst
    sortidx_kernel<<<(nE + 255) / 256, 256>>>(src, dst, nE);
    // 5) per-node gather/mean (fp16 in, fp16 out), writes g_eA[:, 256:512]
    aggregate_kernel<<<(M + 7) / 8, 256>>>(M);
    // 6) encoder GEMM: h = relu(A @ Benc + b_enc), emit h fp16
    {
        dim3 grid(HID_DIM / 128, (M + 127) / 128);
        gemm_mma<true, true><<<grid, 128, SMEM_DYN>>>(
            (const __half*)p_eA, (const __half*)p_be, b_enc, h,
            (__half*)p_hf, M, HID_DIM);
    }
    // 7) decoder GEMM: out = h @ Bdec + b_dec
    {
        dim3 grid(OUT_DIM / 128, (M + 127) / 128);
        gemm_mma<false, false><<<grid, 128, SMEM_DYN>>>(
            (const __half*)p_hf, (const __half*)p_bd, b_dec, out,
            nullptr, M, OUT_DIM);
    }
}

// round 10
// speedup vs baseline: 2.0639x; 1.0007x over previous
#include <cuda_runtime.h>
#include <cuda_fp16.h>
#include <cstdint>

// ---------------------------------------------------------------------------
// GraphAutoencoder (sm_100 base), R10:
//  [streamA: hist -> scan -> sortidx] || [stream0: fp16 convert/pack]
//  -> join -> unrolled gather aggregate -> fp16 mma.sync GEMMs.
// ---------------------------------------------------------------------------

#define N_NODES_MAX 50000
#define N_EDGES_MAX 1000000
#define IN_DIM      256
#define HID_DIM     512
#define OUT_DIM     256
#define KDIM        512
#define NCH         16           // KDIM / 32

// ------------------------------ scratch ------------------------------------
__device__ int g_cnt[N_NODES_MAX];
__device__ int g_offs[N_NODES_MAX + 1];
__device__ int g_cur[N_NODES_MAX];
__device__ int g_srt[N_EDGES_MAX];
__device__ __align__(16) __half g_eA[N_NODES_MAX * KDIM];     // [x | nmean] fp16
__device__ __align__(16) __half g_hf[N_NODES_MAX * HID_DIM];  // h fp16
__device__ __align__(16) __half g_Benc[KDIM * HID_DIM];
__device__ __align__(16) __half g_Bdec[KDIM * OUT_DIM];
__device__ __align__(16) float g_hfb[N_NODES_MAX * HID_DIM];

// --------------------------- asm helpers -----------------------------------
__device__ __forceinline__ uint32_t smem_u32(const void* p) {
    uint32_t a;
    asm("{ .reg .u64 t; cvta.to.shared.u64 t, %1; cvt.u32.u64 %0, t; }"
        : "=r"(a) : "l"(p));
    return a;
}
__device__ __forceinline__ void cp16(uint32_t dst, const void* src, uint32_t srcsize) {
    asm volatile("cp.async.cg.shared.global [%0], [%1], 16, %2;"
                 :: "r"(dst), "l"(src), "r"(srcsize) : "memory");
}
__device__ __forceinline__ void cp_commit() {
    asm volatile("cp.async.commit_group;" ::: "memory");
}
template <int N>
__device__ __forceinline__ void cp_wait() {
    asm volatile("cp.async.wait_group %0;" :: "n"(N) : "memory");
}
#define LDSM_X4(r0, r1, r2, r3, a) \
    asm volatile("ldmatrix.sync.aligned.m8n8.x4.shared.b16 {%0,%1,%2,%3}, [%4];" \
                 : "=r"(r0), "=r"(r1), "=r"(r2), "=r"(r3) : "r"(a))
#define LDSM_X4_T(r0, r1, r2, r3, a) \
    asm volatile("ldmatrix.sync.aligned.m8n8.x4.trans.shared.b16 {%0,%1,%2,%3}, [%4];" \
                 : "=r"(r0), "=r"(r1), "=r"(r2), "=r"(r3) : "r"(a))
#define MMA16816(c, a0, a1, a2, a3, b0, b1) \
    asm volatile("mma.sync.aligned.m16n8k16.row.col.f32.f16.f16.f32 " \
                 "{%0,%1,%2,%3}, {%4,%5,%6,%7}, {%8,%9}, {%0,%1,%2,%3};" \
                 : "+f"((c)[0]), "+f"((c)[1]), "+f"((c)[2]), "+f"((c)[3]) \
                 : "r"(a0), "r"(a1), "r"(a2), "r"(a3), "r"(b0), "r"(b1))

// ----------------------------- prep kernels --------------------------------
__global__ void prep0_kernel(const float* __restrict__ x,
                             const float* __restrict__ Wself,
                             const float* __restrict__ Wneigh,
                             const float* __restrict__ Wdec, int M) {
    int i = blockIdx.x * blockDim.x + threadIdx.x;
    int nx = M * IN_DIM;
    if (i < nx) {
        int r = i >> 8, c = i & 255;
        g_eA[(size_t)r * KDIM + c] = __float2half(x[i]);
        return;
    }
    int j = i - nx;
    if (j < KDIM * HID_DIM) {
        int k = j >> 9, n = j & 511;
        float w = (k < 256) ? Wself[k * HID_DIM + n] : Wneigh[(k - 256) * HID_DIM + n];
        g_Benc[j] = __float2half(w);
        return;
    }
    j -= KDIM * HID_DIM;
    if (j < KDIM * OUT_DIM) {
        int k = j >> 8, n = j & 255;
        g_Bdec[j] = __float2half(Wdec[k * OUT_DIM + n]);
    }
}

__global__ void hist_kernel(const int* __restrict__ dst, int n_edges) {
    int i = blockIdx.x * blockDim.x + threadIdx.x;
    if (i < n_edges) atomicAdd(&g_cnt[dst[i]], 1);
}

__global__ __launch_bounds__(1024)
void scan_kernel(int M) {
    __shared__ int sums[1024];
    int t = threadIdx.x;
    int chunk = (M + 1023) / 1024;
    int base = t * chunk;
    int s = 0;
    for (int i = 0; i < chunk; i++) {
        int idx = base + i;
        if (idx < M) s += g_cnt[idx];
    }
    sums[t] = s;
    __syncthreads();
    for (int d = 1; d < 1024; d <<= 1) {
        int v = (t >= d) ? sums[t - d] : 0;
        __syncthreads();
        sums[t] += v;
        __syncthreads();
    }
    int prefix = (t == 0) ? 0 : sums[t - 1];
    for (int i = 0; i < chunk; i++) {
        int idx = base + i;
        if (idx < M) {
            g_offs[idx] = prefix;
            g_cur[idx] = prefix;
            prefix += g_cnt[idx];
        }
    }
    if (t == 1023) g_offs[M] = prefix;
}

__global__ void sortidx_kernel(const int* __restrict__ src,
                               const int* __restrict__ dst, int n_edges) {
    int i = blockIdx.x * blockDim.x + threadIdx.x;
    if (i >= n_edges) return;
    int pos = atomicAdd(&g_cur[dst[i]], 1);
    g_srt[pos] = src[i];
}

// one warp per node, 4-way unrolled gather (MLP=4), fp32 acc, fp16 mean out
__global__ __launch_bounds__(256)
void aggregate_kernel(int M) {
    int wid_in_blk = threadIdx.x >> 5;
    int lane = threadIdx.x & 31;
    int node = blockIdx.x * 8 + wid_in_blk;
    if (node >= M) return;
    int beg = g_offs[node], end = g_offs[node + 1];

    float acc[8] = {0.f, 0.f, 0.f, 0.f, 0.f, 0.f, 0.f, 0.f};
    const __half* base = g_eA;
    int e = beg;
    for (; e + 4 <= end; e += 4) {
        int s0 = g_srt[e + 0], s1 = g_srt[e + 1];
        int s2 = g_srt[e + 2], s3 = g_srt[e + 3];
        uint4 v0 = *reinterpret_cast<const uint4*>(base + (size_t)s0 * KDIM + lane * 8);
        uint4 v1 = *reinterpret_cast<const uint4*>(base + (size_t)s1 * KDIM + lane * 8);
        uint4 v2 = *reinterpret_cast<const uint4*>(base + (size_t)s2 * KDIM + lane * 8);
        uint4 v3 = *reinterpret_cast<const uint4*>(base + (size_t)s3 * KDIM + lane * 8);
        const __half2* h0 = reinterpret_cast<const __half2*>(&v0);
        const __half2* h1 = reinterpret_cast<const __half2*>(&v1);
        const __half2* h2 = reinterpret_cast<const __half2*>(&v2);
        const __half2* h3 = reinterpret_cast<const __half2*>(&v3);
#pragma unroll
        for (int q = 0; q < 4; q++) {
            float2 f0 = __half22float2(h0[q]);
            float2 f1 = __half22float2(h1[q]);
            float2 f2 = __half22float2(h2[q]);
            float2 f3 = __half22float2(h3[q]);
            acc[2 * q + 0] += (f0.x + f1.x) + (f2.x + f3.x);
            acc[2 * q + 1] += (f0.y + f1.y) + (f2.y + f3.y);
        }
    }
    for (; e < end; e++) {
        int s = g_srt[e];
        uint4 v = *reinterpret_cast<const uint4*>(base + (size_t)s * KDIM + lane * 8);
        const __half2* h2p = reinterpret_cast<const __half2*>(&v);
#pragma unroll
        for (int q = 0; q < 4; q++) {
            float2 f = __half22float2(h2p[q]);
            acc[2 * q + 0] += f.x;
            acc[2 * q + 1] += f.y;
        }
    }
    float inv = 1.0f / fmaxf((float)(end - beg), 1.0f);
    __half2 outv[4];
#pragma unroll
    for (int q = 0; q < 4; q++)
        outv[q] = __floats2half2_rn(acc[2 * q] * inv, acc[2 * q + 1] * inv);
    *reinterpret_cast<uint4*>(g_eA + (size_t)node * KDIM + 256 + lane * 8) =
        *reinterpret_cast<uint4*>(outv);
}

// ----------------------------- mma GEMM ------------------------------------
#define A_PITCH 80
#define B_PITCH 272
#define SZA (128 * A_PITCH)
#define SZB (32 * B_PITCH)
#define STAGES 3
#define SMEM_DYN (STAGES * (SZA + SZB))   // 56832 B

template <bool RELU, bool EMITH>
__global__ __launch_bounds__(128, 2)
void gemm_mma(const __half* __restrict__ A,
              const __half* __restrict__ Bp,
              const float* __restrict__ bias,
              float* __restrict__ C,
              __half* __restrict__ oH,
              int M, int N) {
    extern __shared__ __align__(16) unsigned char smem[];
    uint32_t sA = smem_u32(smem);
    uint32_t sB = sA + STAGES * SZA;

    int tid = threadIdx.x;
    int wid = tid >> 5, lane = tid & 31;
    int wm = wid & 1, wn = wid >> 1;
    int rowBase = blockIdx.y * 128;
    int colBase = blockIdx.x * 128;

    float c[4][8][4];
#pragma unroll
    for (int mf = 0; mf < 4; mf++)
#pragma unroll
        for (int nf = 0; nf < 8; nf++)
#pragma unroll
            for (int q = 0; q < 4; q++) c[mf][nf][q] = 0.f;

    auto load_chunk = [&](int buf, int ch) {
        int k0 = ch * 32;
#pragma unroll
        for (int i = 0; i < 4; i++) {
            int idx = tid + i * 128;
            int r = idx >> 2, cs = idx & 3;
            int grow = rowBase + r;
            int srow = grow < M ? grow : M - 1;
            cp16(sA + buf * SZA + r * A_PITCH + cs * 16,
                 A + (size_t)srow * KDIM + k0 + cs * 8,
                 grow < M ? 16u : 0u);
        }
#pragma unroll
        for (int i = 0; i < 4; i++) {
            int idx = tid + i * 128;
            int r = idx >> 4, cs = idx & 15;
            cp16(sB + buf * SZB + r * B_PITCH + cs * 16,
                 Bp + (size_t)(k0 + r) * N + colBase + cs * 8, 16u);
        }
        cp_commit();
    };

    uint32_t aAddr = sA + (wm * 64 + (lane & 15)) * A_PITCH + (lane >> 4) * 16;
    uint32_t bAddr = sB + (lane & 15) * B_PITCH + wn * 128 + (lane >> 4) * 16;

    load_chunk(0, 0);
    load_chunk(1, 1);

    for (int ch = 0; ch < NCH; ch++) {
        int buf = ch % STAGES;
        if (ch == NCH - 1) cp_wait<0>();
        else               cp_wait<1>();
        __syncthreads();
        if (ch + 2 < NCH) load_chunk((ch + 2) % STAGES, ch + 2);

        uint32_t aB = aAddr + buf * SZA;
        uint32_t bB = bAddr + buf * SZB;
#pragma unroll
        for (int kk = 0; kk < 2; kk++) {
            uint32_t a[16];
#pragma unroll
            for (int g = 0; g < 4; g++)
                LDSM_X4(a[4 * g], a[4 * g + 1], a[4 * g + 2], a[4 * g + 3],
                        aB + g * 16 * A_PITCH + kk * 32);
            uint32_t b[16];
#pragma unroll
            for (int p = 0; p < 4; p++)
                LDSM_X4_T(b[4 * p], b[4 * p + 1], b[4 * p + 2], b[4 * p + 3],
                          bB + kk * 16 * B_PITCH + p * 32);
#pragma unroll
            for (int mf = 0; mf < 4; mf++)
#pragma unroll
                for (int nf = 0; nf < 8; nf++) {
                    uint32_t* bp = b + (nf >> 1) * 4 + (nf & 1) * 2;
                    MMA16816(c[mf][nf], a[4 * mf], a[4 * mf + 1],
                             a[4 * mf + 2], a[4 * mf + 3], bp[0], bp[1]);
                }
        }
    }

    int groupID = lane >> 2, tid4 = lane & 3;
#pragma unroll
    for (int mf = 0; mf < 4; mf++) {
        int r0 = rowBase + wm * 64 + mf * 16 + groupID;
#pragma unroll
        for (int nf = 0; nf < 8; nf++) {
            int cb = colBase + wn * 64 + nf * 8 + tid4 * 2;
            float b0 = bias[cb], b1 = bias[cb + 1];
#pragma unroll
            for (int hh = 0; hh < 2; hh++) {
                int r = r0 + hh * 8;
                if (r >= M) continue;
                float v0 = c[mf][nf][2 * hh + 0] + b0;
                float v1 = c[mf][nf][2 * hh + 1] + b1;
                if (RELU) { v0 = fmaxf(v0, 0.f); v1 = fmaxf(v1, 0.f); }
                *reinterpret_cast<float2*>(C + (size_t)r * N + cb) =
                    make_float2(v0, v1);
                if (EMITH) {
                    __half2 hv;
                    hv.x = __float2half(v0);
                    hv.y = __float2half(v1);
                    *reinterpret_cast<__half2*>(oH + (size_t)r * N + cb) = hv;
                }
            }
        }
    }
}

// ------------------------------ launch -------------------------------------
extern "C" void kernel_launch(void* const* d_in, const int* in_sizes, int n_in,
                              void* d_out, int out_size) {
    const float* x       = (const float*)d_in[0];
    const int*   src     = (const int*)d_in[1];
    const int*   dst     = (const int*)d_in[2];
    const float* W_self  = (const float*)d_in[3];
    const float* W_neigh = (const float*)d_in[4];
    const float* b_enc   = (const float*)d_in[5];
    const float* W_dec   = (const float*)d_in[6];
    const float* b_dec   = (const float*)d_in[7];

    int M  = in_sizes[0] / IN_DIM;
    int nE = in_sizes[1];

    float* out = (float*)d_out;
    float* h;
    if (out_size == M * (OUT_DIM + HID_DIM)) {
        h = out + (long long)M * OUT_DIM;
    } else {
        void* p = nullptr;
        cudaGetSymbolAddress(&p, g_hfb);
        h = (float*)p;
    }

    void *p_eA, *p_hf, *p_be, *p_bd, *p_cnt;
    cudaGetSymbolAddress(&p_eA, g_eA);
    cudaGetSymbolAddress(&p_hf, g_hf);
    cudaGetSymbolAddress(&p_be, g_Benc);
    cudaGetSymbolAddress(&p_bd, g_Bdec);
    cudaGetSymbolAddress(&p_cnt, g_cnt);

    cudaFuncSetAttribute(gemm_mma<true, true>,
                         cudaFuncAttributeMaxDynamicSharedMemorySize, SMEM_DYN);
    cudaFuncSetAttribute(gemm_mma<false, false>,
                         cudaFuncAttributeMaxDynamicSharedMemorySize, SMEM_DYN);

    static cudaStream_t sA = nullptr;
    static cudaEvent_t ev0 = nullptr, evA = nullptr;
    if (!sA) {
        cudaStreamCreateWithFlags(&sA, cudaStreamNonBlocking);
        cudaEventCreateWithFlags(&ev0, cudaEventDisableTiming);
        cudaEventCreateWithFlags(&evA, cudaEventDisableTiming);
    }

    // ---- fork: streamA = index chain (dst/src only) ----
    cudaEventRecord(ev0, 0);
    cudaStreamWaitEvent(sA, ev0, 0);
    cudaMemsetAsync(p_cnt, 0, (size_t)M * sizeof(int), sA);
    hist_kernel<<<(nE + 255) / 256, 256, 0, sA>>>(dst, nE);
    scan_kernel<<<1, 1024, 0, sA>>>(M);
    sortidx_kernel<<<(nE + 255) / 256, 256, 0, sA>>>(src, dst, nE);
    cudaEventRecord(evA, sA);

    // ---- stream 0 = fp16 convert + weight packing ----
    {
        int total = M * IN_DIM + KDIM * HID_DIM + KDIM * OUT_DIM;
        prep0_kernel<<<(total + 255) / 256, 256>>>(x, W_self, W_neigh, W_dec, M);
    }

    // ---- join ----
    cudaStreamWaitEvent(0, evA, 0);

    // aggregate -> encoder -> decoder
    aggregate_kernel<<<(M + 7) / 8, 256>>>(M);
    {
        dim3 grid(HID_DIM / 128, (M + 127) / 128);
        gemm_mma<true, true><<<grid, 128, SMEM_DYN>>>(
            (const __half*)p_eA, (const __half*)p_be, b_enc, h,
            (__half*)p_hf, M, HID_DIM);
    }
    {
        dim3 grid(OUT_DIM / 128, (M + 127) / 128);
        gemm_mma<false, false><<<grid, 128, SMEM_DYN>>>(
            (const __half*)p_hf, (const __half*)p_bd, b_dec, out,
            nullptr, M, OUT_DIM);
    }
}

// round 12
// speedup vs baseline: 2.3219x; 1.1250x over previous
#include <cuda_runtime.h>
#include <cuda_fp16.h>
#include <cstdint>

// ---------------------------------------------------------------------------
// GraphAutoencoder (sm_100 base), R12 (= R11 with compile fix):
//  fork A: memset/hist/scan/sortidx            (index chain)
//  fork 0: prep0 (vectorized fp16 convert) -> x-GEMM (K=256, fp16 partial P)
//  aggregate (on A, after prep0) || x-GEMM (on 0)
//  join -> n-GEMM (K=256, reads P, +bias, relu, emits h) -> decoder GEMM.
// ---------------------------------------------------------------------------

#define N_NODES_MAX 50000
#define N_EDGES_MAX 1000000
#define IN_DIM      256
#define HID_DIM     512
#define OUT_DIM     256
#define KDIM        512          // row stride of g_eA

// ------------------------------ scratch ------------------------------------
__device__ int g_cnt[N_NODES_MAX];
__device__ int g_offs[N_NODES_MAX + 1];
__device__ int g_cur[N_NODES_MAX];
__device__ int g_srt[N_EDGES_MAX];
__device__ __align__(16) __half g_eA[N_NODES_MAX * KDIM];     // [x | nmean]
__device__ __align__(16) __half g_hf[N_NODES_MAX * HID_DIM];  // h fp16
__device__ __align__(16) __half g_P[N_NODES_MAX * HID_DIM];   // x@Wself partial
__device__ __align__(16) __half g_Benc[KDIM * HID_DIM];       // [Wself; Wneigh]
__device__ __align__(16) __half g_Bdec[KDIM * OUT_DIM];
__device__ __align__(16) float g_hfb[N_NODES_MAX * HID_DIM];

// --------------------------- asm helpers -----------------------------------
__device__ __forceinline__ uint32_t smem_u32(const void* p) {
    uint32_t a;
    asm("{ .reg .u64 t; cvta.to.shared.u64 t, %1; cvt.u32.u64 %0, t; }"
        : "=r"(a) : "l"(p));
    return a;
}
__device__ __forceinline__ void cp16(uint32_t dst, const void* src, uint32_t srcsize) {
    asm volatile("cp.async.cg.shared.global [%0], [%1], 16, %2;"
                 :: "r"(dst), "l"(src), "r"(srcsize) : "memory");
}
__device__ __forceinline__ void cp_commit() {
    asm volatile("cp.async.commit_group;" ::: "memory");
}
template <int N>
__device__ __forceinline__ void cp_wait() {
    asm volatile("cp.async.wait_group %0;" :: "n"(N) : "memory");
}
#define LDSM_X4(r0, r1, r2, r3, a) \
    asm volatile("ldmatrix.sync.aligned.m8n8.x4.shared.b16 {%0,%1,%2,%3}, [%4];" \
                 : "=r"(r0), "=r"(r1), "=r"(r2), "=r"(r3) : "r"(a))
#define LDSM_X4_T(r0, r1, r2, r3, a) \
    asm volatile("ldmatrix.sync.aligned.m8n8.x4.trans.shared.b16 {%0,%1,%2,%3}, [%4];" \
                 : "=r"(r0), "=r"(r1), "=r"(r2), "=r"(r3) : "r"(a))
#define MMA16816(c, a0, a1, a2, a3, b0, b1) \
    asm volatile("mma.sync.aligned.m16n8k16.row.col.f32.f16.f16.f32 " \
                 "{%0,%1,%2,%3}, {%4,%5,%6,%7}, {%8,%9}, {%0,%1,%2,%3};" \
                 : "+f"((c)[0]), "+f"((c)[1]), "+f"((c)[2]), "+f"((c)[3]) \
                 : "r"(a0), "r"(a1), "r"(a2), "r"(a3), "r"(b0), "r"(b1))

// pack two half2 into uint2 without exotic intrinsics
__device__ __forceinline__ uint2 pack4h(__half2 h0, __half2 h1) {
    uint2 u;
    u.x = *reinterpret_cast<uint32_t*>(&h0);
    u.y = *reinterpret_cast<uint32_t*>(&h1);
    return u;
}

// ----------------------------- prep kernels --------------------------------
// vectorized: 4 floats -> 4 halves per thread
__global__ void prep0_kernel(const float* __restrict__ x,
                             const float* __restrict__ Wself,
                             const float* __restrict__ Wneigh,
                             const float* __restrict__ Wdec, int M) {
    int i = blockIdx.x * blockDim.x + threadIdx.x;
    int nx4 = M * (IN_DIM / 4);
    if (i < nx4) {
        int r = i >> 6, c4 = (i & 63) * 4;          // IN_DIM/4 = 64
        float4 v = reinterpret_cast<const float4*>(x)[i];
        *reinterpret_cast<uint2*>(g_eA + (size_t)r * KDIM + c4) =
            pack4h(__floats2half2_rn(v.x, v.y), __floats2half2_rn(v.z, v.w));
        return;
    }
    int j = i - nx4;
    int nbe4 = (KDIM * HID_DIM) / 4;
    if (j < nbe4) {
        int k = j >> 7, n4 = (j & 127) * 4;         // HID_DIM/4 = 128
        const float* Wrow = (k < 256) ? (Wself + (size_t)k * HID_DIM)
                                      : (Wneigh + (size_t)(k - 256) * HID_DIM);
        float4 v = *reinterpret_cast<const float4*>(Wrow + n4);
        *reinterpret_cast<uint2*>(g_Benc + (size_t)k * HID_DIM + n4) =
            pack4h(__floats2half2_rn(v.x, v.y), __floats2half2_rn(v.z, v.w));
        return;
    }
    j -= nbe4;
    int nbd4 = (KDIM * OUT_DIM) / 4;
    if (j < nbd4) {
        int k = j >> 6, n4 = (j & 63) * 4;          // OUT_DIM/4 = 64
        float4 v = *reinterpret_cast<const float4*>(Wdec + (size_t)k * OUT_DIM + n4);
        *reinterpret_cast<uint2*>(g_Bdec + (size_t)k * OUT_DIM + n4) =
            pack4h(__floats2half2_rn(v.x, v.y), __floats2half2_rn(v.z, v.w));
    }
}

__global__ void hist_kernel(const int* __restrict__ dst, int n_edges) {
    int i = blockIdx.x * blockDim.x + threadIdx.x;
    if (i < n_edges) atomicAdd(&g_cnt[dst[i]], 1);
}

__global__ __launch_bounds__(1024)
void scan_kernel(int M) {
    __shared__ int sums[1024];
    int t = threadIdx.x;
    int chunk = (M + 1023) / 1024;
    int base = t * chunk;
    int s = 0;
    for (int i = 0; i < chunk; i++) {
        int idx = base + i;
        if (idx < M) s += g_cnt[idx];
    }
    sums[t] = s;
    __syncthreads();
    for (int d = 1; d < 1024; d <<= 1) {
        int v = (t >= d) ? sums[t - d] : 0;
        __syncthreads();
        sums[t] += v;
        __syncthreads();
    }
    int prefix = (t == 0) ? 0 : sums[t - 1];
    for (int i = 0; i < chunk; i++) {
        int idx = base + i;
        if (idx < M) {
            g_offs[idx] = prefix;
            g_cur[idx] = prefix;
            prefix += g_cnt[idx];
        }
    }
    if (t == 1023) g_offs[M] = prefix;
}

__global__ void sortidx_kernel(const int* __restrict__ src,
                               const int* __restrict__ dst, int n_edges) {
    int i = blockIdx.x * blockDim.x + threadIdx.x;
    if (i >= n_edges) return;
    int pos = atomicAdd(&g_cur[dst[i]], 1);
    g_srt[pos] = src[i];
}

// one warp per node: gather fp16 x rows, fp32 acc, write fp16 mean
__global__ __launch_bounds__(256)
void aggregate_kernel(int M) {
    int wid_in_blk = threadIdx.x >> 5;
    int lane = threadIdx.x & 31;
    int node = blockIdx.x * 8 + wid_in_blk;
    if (node >= M) return;
    int beg = g_offs[node], end = g_offs[node + 1];

    float acc[8] = {0.f, 0.f, 0.f, 0.f, 0.f, 0.f, 0.f, 0.f};
    int e = beg;
    for (; e + 2 <= end; e += 2) {
        int s0 = g_srt[e + 0], s1 = g_srt[e + 1];
        uint4 v0 = *reinterpret_cast<const uint4*>(g_eA + (size_t)s0 * KDIM + lane * 8);
        uint4 v1 = *reinterpret_cast<const uint4*>(g_eA + (size_t)s1 * KDIM + lane * 8);
        const __half2* h0 = reinterpret_cast<const __half2*>(&v0);
        const __half2* h1 = reinterpret_cast<const __half2*>(&v1);
#pragma unroll
        for (int q = 0; q < 4; q++) {
            float2 f0 = __half22float2(h0[q]);
            float2 f1 = __half22float2(h1[q]);
            acc[2 * q + 0] += f0.x + f1.x;
            acc[2 * q + 1] += f0.y + f1.y;
        }
    }
    if (e < end) {
        int s = g_srt[e];
        uint4 v = *reinterpret_cast<const uint4*>(g_eA + (size_t)s * KDIM + lane * 8);
        const __half2* hp = reinterpret_cast<const __half2*>(&v);
#pragma unroll
        for (int q = 0; q < 4; q++) {
            float2 f = __half22float2(hp[q]);
            acc[2 * q + 0] += f.x;
            acc[2 * q + 1] += f.y;
        }
    }
    float inv = 1.0f / fmaxf((float)(end - beg), 1.0f);
    __half2 outv[4];
#pragma unroll
    for (int q = 0; q < 4; q++)
        outv[q] = __floats2half2_rn(acc[2 * q] * inv, acc[2 * q + 1] * inv);
    *reinterpret_cast<uint4*>(g_eA + (size_t)node * KDIM + 256 + lane * 8) =
        *reinterpret_cast<uint4*>(outv);
}

// ----------------------------- mma GEMM ------------------------------------
// CTA 128x128, 4 warps (2x2, 64x64), BK=32, 3-stage pipe. A row stride = 512.
// MODE 0: partial -> write fp16 P only (no bias/relu)
// MODE 1: final  -> read fp16 P, +bias, relu, write fp32 C + fp16 h
// MODE 2: final  -> +bias, write fp32 C only
#define A_PITCH 80
#define B_PITCH 272
#define SZA (128 * A_PITCH)
#define SZB (32 * B_PITCH)
#define STAGES 3
#define SMEM_DYN (STAGES * (SZA + SZB))   // 56832 B

template <int NCH, int MODE>
__global__ __launch_bounds__(128, 2)
void gemm_mma(const __half* __restrict__ A,
              const __half* __restrict__ Bp,
              const float* __restrict__ bias,
              const __half* __restrict__ Pin,
              float* __restrict__ C,
              __half* __restrict__ oH,
              int M, int N) {
    extern __shared__ __align__(16) unsigned char smem[];
    uint32_t sA = smem_u32(smem);
    uint32_t sB = sA + STAGES * SZA;

    int tid = threadIdx.x;
    int wid = tid >> 5, lane = tid & 31;
    int wm = wid & 1, wn = wid >> 1;
    int rowBase = blockIdx.y * 128;
    int colBase = blockIdx.x * 128;

    float c[4][8][4];
#pragma unroll
    for (int mf = 0; mf < 4; mf++)
#pragma unroll
        for (int nf = 0; nf < 8; nf++)
#pragma unroll
            for (int q = 0; q < 4; q++) c[mf][nf][q] = 0.f;

    auto load_chunk = [&](int buf, int ch) {
        int k0 = ch * 32;
#pragma unroll
        for (int i = 0; i < 4; i++) {
            int idx = tid + i * 128;
            int r = idx >> 2, cs = idx & 3;
            int grow = rowBase + r;
            int srow = grow < M ? grow : M - 1;
            cp16(sA + buf * SZA + r * A_PITCH + cs * 16,
                 A + (size_t)srow * KDIM + k0 + cs * 8,
                 grow < M ? 16u : 0u);
        }
#pragma unroll
        for (int i = 0; i < 4; i++) {
            int idx = tid + i * 128;
            int r = idx >> 4, cs = idx & 15;
            cp16(sB + buf * SZB + r * B_PITCH + cs * 16,
                 Bp + (size_t)(k0 + r) * N + colBase + cs * 8, 16u);
        }
        cp_commit();
    };

    uint32_t aAddr = sA + (wm * 64 + (lane & 15)) * A_PITCH + (lane >> 4) * 16;
    uint32_t bAddr = sB + (lane & 15) * B_PITCH + wn * 128 + (lane >> 4) * 16;

    load_chunk(0, 0);
    load_chunk(1, 1);

    for (int ch = 0; ch < NCH; ch++) {
        int buf = ch % STAGES;
        if (ch == NCH - 1) cp_wait<0>();
        else               cp_wait<1>();
        __syncthreads();
        if (ch + 2 < NCH) load_chunk((ch + 2) % STAGES, ch + 2);

        uint32_t aB = aAddr + buf * SZA;
        uint32_t bB = bAddr + buf * SZB;
#pragma unroll
        for (int kk = 0; kk < 2; kk++) {
            uint32_t a[16];
#pragma unroll
            for (int g = 0; g < 4; g++)
                LDSM_X4(a[4 * g], a[4 * g + 1], a[4 * g + 2], a[4 * g + 3],
                        aB + g * 16 * A_PITCH + kk * 32);
            uint32_t b[16];
#pragma unroll
            for (int p = 0; p < 4; p++)
                LDSM_X4_T(b[4 * p], b[4 * p + 1], b[4 * p + 2], b[4 * p + 3],
                          bB + kk * 16 * B_PITCH + p * 32);
#pragma unroll
            for (int mf = 0; mf < 4; mf++)
#pragma unroll
                for (int nf = 0; nf < 8; nf++) {
                    uint32_t* bp = b + (nf >> 1) * 4 + (nf & 1) * 2;
                    MMA16816(c[mf][nf], a[4 * mf], a[4 * mf + 1],
                             a[4 * mf + 2], a[4 * mf + 3], bp[0], bp[1]);
                }
        }
    }

    // ---- epilogue ----
    int groupID = lane >> 2, tid4 = lane & 3;
#pragma unroll
    for (int mf = 0; mf < 4; mf++) {
        int r0 = rowBase + wm * 64 + mf * 16 + groupID;
#pragma unroll
        for (int nf = 0; nf < 8; nf++) {
            int cb = colBase + wn * 64 + nf * 8 + tid4 * 2;
            float b0 = 0.f, b1 = 0.f;
            if (MODE != 0) { b0 = bias[cb]; b1 = bias[cb + 1]; }
#pragma unroll
            for (int hh = 0; hh < 2; hh++) {
                int r = r0 + hh * 8;
                if (r >= M) continue;
                float v0 = c[mf][nf][2 * hh + 0] + b0;
                float v1 = c[mf][nf][2 * hh + 1] + b1;
                if (MODE == 0) {
                    __half2 pv;
                    pv.x = __float2half(v0);
                    pv.y = __float2half(v1);
                    *reinterpret_cast<__half2*>(oH + (size_t)r * N + cb) = pv;
                } else if (MODE == 1) {
                    __half2 pv = *reinterpret_cast<const __half2*>(
                        Pin + (size_t)r * N + cb);
                    v0 += __half2float(pv.x);
                    v1 += __half2float(pv.y);
                    v0 = fmaxf(v0, 0.f);
                    v1 = fmaxf(v1, 0.f);
                    *reinterpret_cast<float2*>(C + (size_t)r * N + cb) =
                        make_float2(v0, v1);
                    __half2 hv;
                    hv.x = __float2half(v0);
                    hv.y = __float2half(v1);
                    *reinterpret_cast<__half2*>(oH + (size_t)r * N + cb) = hv;
                } else {
                    *reinterpret_cast<float2*>(C + (size_t)r * N + cb) =
                        make_float2(v0, v1);
                }
            }
        }
    }
}

// ------------------------------ launch -------------------------------------
extern "C" void kernel_launch(void* const* d_in, const int* in_sizes, int n_in,
                              void* d_out, int out_size) {
    const float* x       = (const float*)d_in[0];
    const int*   src     = (const int*)d_in[1];
    const int*   dst     = (const int*)d_in[2];
    const float* W_self  = (const float*)d_in[3];
    const float* W_neigh = (const float*)d_in[4];
    const float* b_enc   = (const float*)d_in[5];
    const float* W_dec   = (const float*)d_in[6];
    const float* b_dec   = (const float*)d_in[7];

    int M  = in_sizes[0] / IN_DIM;
    int nE = in_sizes[1];

    float* out = (float*)d_out;
    float* h;
    if (out_size == M * (OUT_DIM + HID_DIM)) {
        h = out + (long long)M * OUT_DIM;
    } else {
        void* p = nullptr;
        cudaGetSymbolAddress(&p, g_hfb);
        h = (float*)p;
    }

    void *p_eA, *p_hf, *p_P, *p_be, *p_bd, *p_cnt;
    cudaGetSymbolAddress(&p_eA, g_eA);
    cudaGetSymbolAddress(&p_hf, g_hf);
    cudaGetSymbolAddress(&p_P, g_P);
    cudaGetSymbolAddress(&p_be, g_Benc);
    cudaGetSymbolAddress(&p_bd, g_Bdec);
    cudaGetSymbolAddress(&p_cnt, g_cnt);

    cudaFuncSetAttribute(gemm_mma<8, 0>,
                         cudaFuncAttributeMaxDynamicSharedMemorySize, SMEM_DYN);
    cudaFuncSetAttribute(gemm_mma<8, 1>,
                         cudaFuncAttributeMaxDynamicSharedMemorySize, SMEM_DYN);
    cudaFuncSetAttribute(gemm_mma<16, 2>,
                         cudaFuncAttributeMaxDynamicSharedMemorySize, SMEM_DYN);

    static cudaStream_t sA = nullptr;
    static cudaEvent_t ev0 = nullptr, evP = nullptr, evA = nullptr;
    if (!sA) {
        cudaStreamCreateWithFlags(&sA, cudaStreamNonBlocking);
        cudaEventCreateWithFlags(&ev0, cudaEventDisableTiming);
        cudaEventCreateWithFlags(&evP, cudaEventDisableTiming);
        cudaEventCreateWithFlags(&evA, cudaEventDisableTiming);
    }

    // ---- fork: streamA = index chain ----
    cudaEventRecord(ev0, 0);
    cudaStreamWaitEvent(sA, ev0, 0);
    cudaMemsetAsync(p_cnt, 0, (size_t)M * sizeof(int), sA);
    hist_kernel<<<(nE + 255) / 256, 256, 0, sA>>>(dst, nE);
    scan_kernel<<<1, 1024, 0, sA>>>(M);
    sortidx_kernel<<<(nE + 255) / 256, 256, 0, sA>>>(src, dst, nE);

    // ---- stream 0: prep (vectorized) ----
    {
        int total = M * (IN_DIM / 4) + (KDIM * HID_DIM) / 4 + (KDIM * OUT_DIM) / 4;
        prep0_kernel<<<(total + 255) / 256, 256>>>(x, W_self, W_neigh, W_dec, M);
    }
    cudaEventRecord(evP, 0);
    cudaStreamWaitEvent(sA, evP, 0);

    // ---- streamA: aggregate (needs index chain + prep0's x part) ----
    aggregate_kernel<<<(M + 7) / 8, 256, 0, sA>>>(M);
    cudaEventRecord(evA, sA);

    // ---- stream 0 (concurrent with aggregate): x-part GEMM -> fp16 P ----
    {
        dim3 grid(HID_DIM / 128, (M + 127) / 128);
        gemm_mma<8, 0><<<grid, 128, SMEM_DYN>>>(
            (const __half*)p_eA, (const __half*)p_be, nullptr, nullptr,
            nullptr, (__half*)p_P, M, HID_DIM);
    }

    // ---- join: n-part GEMM (reads P), then decoder ----
    cudaStreamWaitEvent(0, evA, 0);
    {
        dim3 grid(HID_DIM / 128, (M + 127) / 128);
        gemm_mma<8, 1><<<grid, 128, SMEM_DYN>>>(
            (const __half*)p_eA + 256,
            (const __half*)p_be + (size_t)256 * HID_DIM,
            b_enc, (const __half*)p_P, h, (__half*)p_hf, M, HID_DIM);
    }
    {
        dim3 grid(OUT_DIM / 128, (M + 127) / 128);
        gemm_mma<16, 2><<<grid, 128, SMEM_DYN>>>(
            (const __half*)p_hf, (const __half*)p_bd, b_dec, nullptr,
            out, nullptr, M, OUT_DIM);
    }
}